// round 1
// baseline (speedup 1.0000x reference)
#include <cuda_runtime.h>
#include <cstdint>
#include <cstddef>

#define N_NODES 19
#define NI      128
#define NO      512
#define KDIM    (N_NODES * NI)   // 2432
#define BSZ     16384
#define VOCAB   20000

#define BM 128
#define BN 128
#define BK 16

// Scratch: converted int32 indices + dtype flag (no allocations allowed).
__device__ int g_idx32[BSZ * N_NODES];
__device__ int g_is64;

// ---------------------------------------------------------------------------
// Prologue: detect whether `feature` is int64 or int32, convert to int32.
// If the data is really int64, every value (as u64) is < VOCAB. If it is
// int32, u64 reinterpretation pairs two random indices -> almost surely
// >= 2^32 somewhere in 155k samples. We only read the first half of the
// element count as u64 so we never read past an int32-sized buffer.
// ---------------------------------------------------------------------------
__global__ void k_init_flag() {
    if (threadIdx.x == 0) g_is64 = 1;
}

__global__ void k_detect(const unsigned long long* __restrict__ f) {
    const int half = BSZ * N_NODES / 2;
    int i = blockIdx.x * blockDim.x + threadIdx.x;
    if (i < half) {
        if (f[i] >= (unsigned long long)VOCAB) g_is64 = 0;  // race-benign store
    }
}

__global__ void k_convert(const void* __restrict__ f) {
    int i = blockIdx.x * blockDim.x + threadIdx.x;
    if (i < BSZ * N_NODES) {
        int v;
        if (g_is64) v = (int)((const long long*)f)[i];
        else        v = ((const int*)f)[i];
        g_idx32[i] = v;
    }
}

// ---------------------------------------------------------------------------
// Fused gather + SGEMM.
// A[m, k] = emb[k/128, feature[m, k/128], k%128]   (virtual, gathered on load)
// B[n, k] = fc_w[n, k]
// out[m, n] = sum_k A[m,k] * B[n,k] + bias[n]
// 128x128 CTA tile, BK=16 (one k-tile never crosses a node boundary since
// 128 % 16 == 0), 256 threads, 8x8 per-thread microtile.
// ---------------------------------------------------------------------------
__global__ __launch_bounds__(256, 2)
void k_gemm(const float* __restrict__ emb, const float* __restrict__ w,
            const float* __restrict__ bias, float* __restrict__ out)
{
    __shared__ float As[BK][BM];          // A transposed: As[k][m]
    __shared__ float Bs[BK][BN];          // B transposed: Bs[k][n]
    __shared__ int   idxS[BM][N_NODES];   // per-row gather indices

    const int tid = threadIdx.x;
    const int m0 = blockIdx.y * BM;
    const int n0 = blockIdx.x * BN;

    // Stage this CTA's gather indices once.
    for (int i = tid; i < BM * N_NODES; i += 256) {
        idxS[i / N_NODES][i % N_NODES] = g_idx32[(m0 + i / N_NODES) * N_NODES + i % N_NODES];
    }
    __syncthreads();

    const int lrow = tid >> 2;          // 0..63   (row within tile for loads)
    const int lcol = (tid & 3) << 2;    // 0,4,8,12 (k offset, float4 granule)

    const int ty = tid >> 4;            // 0..15 -> m block
    const int tx = tid & 15;            // 0..15 -> n block

    float acc[8][8];
    #pragma unroll
    for (int i = 0; i < 8; i++)
        #pragma unroll
        for (int j = 0; j < 8; j++)
            acc[i][j] = 0.0f;

    for (int k0 = 0; k0 < KDIM; k0 += BK) {
        const int node = k0 >> 7;          // which embedding node this k-tile is in
        const int koff = (k0 & 127) + lcol;

        #pragma unroll
        for (int s = 0; s < 2; s++) {
            const int r = lrow + s * 64;
            // A: gather 4 floats of the embedding row for CTA-row r
            const float* asrc = emb + ((size_t)node * VOCAB + idxS[r][node]) * NI + koff;
            const float4 va = *(const float4*)asrc;
            As[lcol + 0][r] = va.x;
            As[lcol + 1][r] = va.y;
            As[lcol + 2][r] = va.z;
            As[lcol + 3][r] = va.w;
            // B: fc_w row n0+r, k-slice
            const float4 vb = *(const float4*)(w + (size_t)(n0 + r) * KDIM + k0 + lcol);
            Bs[lcol + 0][r] = vb.x;
            Bs[lcol + 1][r] = vb.y;
            Bs[lcol + 2][r] = vb.z;
            Bs[lcol + 3][r] = vb.w;
        }
        __syncthreads();

        #pragma unroll
        for (int kk = 0; kk < BK; kk++) {
            const float4 a0 = *(const float4*)&As[kk][ty * 8];
            const float4 a1 = *(const float4*)&As[kk][ty * 8 + 4];
            const float4 b0 = *(const float4*)&Bs[kk][tx * 8];
            const float4 b1 = *(const float4*)&Bs[kk][tx * 8 + 4];
            const float a[8] = {a0.x, a0.y, a0.z, a0.w, a1.x, a1.y, a1.z, a1.w};
            const float b[8] = {b0.x, b0.y, b0.z, b0.w, b1.x, b1.y, b1.z, b1.w};
            #pragma unroll
            for (int i = 0; i < 8; i++)
                #pragma unroll
                for (int j = 0; j < 8; j++)
                    acc[i][j] += a[i] * b[j];
        }
        __syncthreads();
    }

    // Epilogue: add bias, store float4.
    #pragma unroll
    for (int i = 0; i < 8; i++) {
        const int m = m0 + ty * 8 + i;
        #pragma unroll
        for (int j = 0; j < 8; j += 4) {
            const float4 bb = *(const float4*)(bias + n0 + tx * 8 + j);
            float4 v;
            v.x = acc[i][j + 0] + bb.x;
            v.y = acc[i][j + 1] + bb.y;
            v.z = acc[i][j + 2] + bb.z;
            v.w = acc[i][j + 3] + bb.w;
            *(float4*)(out + (size_t)m * NO + n0 + tx * 8 + j) = v;
        }
    }
}

// ---------------------------------------------------------------------------
extern "C" void kernel_launch(void* const* d_in, const int* in_sizes, int n_in,
                              void* d_out, int out_size)
{
    (void)in_sizes; (void)n_in; (void)out_size;
    const void*  feat = d_in[0];                  // feature [16384, 19] int64/int32
    const float* emb  = (const float*)d_in[1];    // [19, 20000, 128] f32
    const float* w    = (const float*)d_in[2];    // [512, 2432] f32
    const float* bias = (const float*)d_in[3];    // [512] f32
    float* out = (float*)d_out;                   // [16384, 512] f32

    k_init_flag<<<1, 32>>>();
    {
        const int half = BSZ * N_NODES / 2;
        k_detect<<<(half + 255) / 256, 256>>>((const unsigned long long*)feat);
    }
    k_convert<<<(BSZ * N_NODES + 255) / 256, 256>>>(feat);

    dim3 grid(NO / BN, BSZ / BM);
    k_gemm<<<grid, 256>>>(emb, w, bias, out);
}

// round 4
// speedup vs baseline: 1.9983x; 1.9983x over previous
#include <cuda_runtime.h>
#include <cuda_bf16.h>
#include <cstdint>
#include <cstddef>

#define N_NODES 19
#define NI      128
#define NO      512
#define KDIM    2432
#define BSZ     16384
#define VOCAB   20000

#define BM      128
#define BN      128
#define BK      32                 // bf16 k-chunk
#define NITER   (KDIM / BK)        // 76
#define THREADS 256

// ---- dynamic smem layout ----
#define ROWB        80                      // padded row pitch (bytes): 32 bf16 + 16B pad
#define OFF_IDX     0                       // 19*128*4 = 9728 B
#define OFF_STAGE   10240
#define STG_AH      0                       // 128*80 = 10240 B each
#define STG_AL      10240
#define STG_BH      20480
#define STG_BL      30720
#define STAGE_BYTES 40960
#define SMEM_ALLOC  (OFF_STAGE + 2 * STAGE_BYTES)   // 92160

// ---- global scratch ----
__device__ int g_idx32[BSZ * N_NODES];
__device__ int g_is64;
__device__ __align__(16) __nv_bfloat16 g_whi[NO * KDIM];
__device__ __align__(16) __nv_bfloat16 g_wlo[NO * KDIM];

// ===========================================================================
// helpers
// ===========================================================================
__device__ __forceinline__ void sts128(uint32_t addr, uint32_t a, uint32_t b,
                                       uint32_t c, uint32_t d) {
    asm volatile("st.shared.v4.b32 [%0], {%1,%2,%3,%4};"
                 :: "r"(addr), "r"(a), "r"(b), "r"(c), "r"(d));
}

__device__ __forceinline__ void ldmx4(uint32_t& r0, uint32_t& r1, uint32_t& r2,
                                      uint32_t& r3, uint32_t addr) {
    asm volatile("ldmatrix.sync.aligned.m8n8.x4.shared.b16 {%0,%1,%2,%3}, [%4];"
                 : "=r"(r0), "=r"(r1), "=r"(r2), "=r"(r3) : "r"(addr));
}

__device__ __forceinline__ void mma16816(float& d0, float& d1, float& d2, float& d3,
                                         uint32_t a0, uint32_t a1, uint32_t a2, uint32_t a3,
                                         uint32_t b0, uint32_t b1) {
    asm volatile("mma.sync.aligned.m16n8k16.row.col.f32.bf16.bf16.f32 "
                 "{%0,%1,%2,%3}, {%4,%5,%6,%7}, {%8,%9}, {%0,%1,%2,%3};"
                 : "+f"(d0), "+f"(d1), "+f"(d2), "+f"(d3)
                 : "r"(a0), "r"(a1), "r"(a2), "r"(a3), "r"(b0), "r"(b1));
}

__device__ __forceinline__ uint32_t pack_bf2(float x, float y) {
    __nv_bfloat162 h = __floats2bfloat162_rn(x, y);
    return *reinterpret_cast<uint32_t*>(&h);
}

// split float4 into hi bf16x2 words (h01,h23) and lo residual words (l01,l23)
__device__ __forceinline__ void split4(float4 v, uint32_t& h01, uint32_t& h23,
                                       uint32_t& l01, uint32_t& l23) {
    __nv_bfloat16 a = __float2bfloat16_rn(v.x);
    __nv_bfloat16 b = __float2bfloat16_rn(v.y);
    __nv_bfloat16 c = __float2bfloat16_rn(v.z);
    __nv_bfloat16 d = __float2bfloat16_rn(v.w);
    h01 = ((uint32_t)__bfloat16_as_ushort(b) << 16) | __bfloat16_as_ushort(a);
    h23 = ((uint32_t)__bfloat16_as_ushort(d) << 16) | __bfloat16_as_ushort(c);
    l01 = pack_bf2(v.x - __bfloat162float(a), v.y - __bfloat162float(b));
    l23 = pack_bf2(v.z - __bfloat162float(c), v.w - __bfloat162float(d));
}

// ===========================================================================
// prologue kernels
// ===========================================================================
__global__ void k_init_flag() { if (threadIdx.x == 0) g_is64 = 1; }

__global__ void k_detect(const unsigned long long* __restrict__ f) {
    const int half = BSZ * N_NODES / 2;
    int i = blockIdx.x * blockDim.x + threadIdx.x;
    if (i < half && f[i] >= (unsigned long long)VOCAB) g_is64 = 0;
}

__global__ void k_convert(const void* __restrict__ f) {
    int i = blockIdx.x * blockDim.x + threadIdx.x;
    if (i < BSZ * N_NODES) {
        g_idx32[i] = g_is64 ? (int)((const long long*)f)[i] : ((const int*)f)[i];
    }
}

__global__ void k_splitw(const float* __restrict__ w) {
    int i = blockIdx.x * blockDim.x + threadIdx.x;
    if (i < NO * KDIM) {
        float v = w[i];
        __nv_bfloat16 h = __float2bfloat16_rn(v);
        g_whi[i] = h;
        g_wlo[i] = __float2bfloat16_rn(v - __bfloat162float(h));
    }
}

// ===========================================================================
// fused gather + bf16-split HMMA GEMM
// ===========================================================================
__global__ __launch_bounds__(THREADS, 1)
void k_gemm(const float* __restrict__ emb, const float* __restrict__ bias,
            float* __restrict__ out)
{
    extern __shared__ char smem[];
    const uint32_t sb = (uint32_t)__cvta_generic_to_shared(smem);

    const int tid = threadIdx.x;
    const int wid = tid >> 5;
    const int lid = tid & 31;
    const int m0 = blockIdx.y * BM;
    const int n0 = blockIdx.x * BN;
    const int wm = wid >> 2;       // 0..1 -> warp m block (64 rows)
    const int wn = wid & 3;        // 0..3 -> warp n block (32 cols)

    // stage gather indices: idxS[node][row]
    int* idxS = (int*)(smem + OFF_IDX);
    for (int i = tid; i < N_NODES * BM; i += THREADS) {
        int node = i >> 7, r = i & 127;
        idxS[node * BM + r] = g_idx32[(m0 + r) * N_NODES + node];
    }
    __syncthreads();

    // ---- per-thread load roles ----
    const int arow = tid & 127;        // A row
    const int ahalf = tid >> 7;        // 0/1 -> 16-float half of BK=32
    const int brow = tid >> 2;         // B row (and brow+64)
    const int bc = tid & 3;            // 16B chunk within 64B row

    float4 areg[4];                    // 16 fp32 of A
    uint4  bh0, bh1, bl0, bl1;         // B hi/lo 16B chunks (2 rows)

    auto load_regs = [&](int it) {
        const int k0 = it * BK;
        const int node = k0 >> 7;
        const float* ap = emb +
            ((size_t)node * VOCAB + idxS[node * BM + arow]) * NI + (k0 & 127) + ahalf * 16;
        #pragma unroll
        for (int i = 0; i < 4; i++) areg[i] = ((const float4*)ap)[i];
        const size_t bo0 = (size_t)(n0 + brow) * KDIM + k0 + bc * 8;
        const size_t bo1 = (size_t)(n0 + brow + 64) * KDIM + k0 + bc * 8;
        bh0 = *(const uint4*)(g_whi + bo0);
        bh1 = *(const uint4*)(g_whi + bo1);
        bl0 = *(const uint4*)(g_wlo + bo0);
        bl1 = *(const uint4*)(g_wlo + bo1);
    };

    float acc[4][4][4];                // [mi][ni][frag]
    #pragma unroll
    for (int i = 0; i < 4; i++)
        #pragma unroll
        for (int j = 0; j < 4; j++)
            #pragma unroll
            for (int q = 0; q < 4; q++)
                acc[i][j][q] = 0.0f;

    load_regs(0);

    // ldmatrix lane address components (row = base + (lid&15), colhalf = (lid>>4)*16B)
    const uint32_t lrow = (uint32_t)(lid & 15);
    const uint32_t lcolh = (uint32_t)((lid >> 4) * 16);

    for (int it = 0; it < NITER; it++) {
        const uint32_t st = sb + OFF_STAGE + (it & 1) * STAGE_BYTES;

        // 1. STS staged registers -> smem (stage s)
        {
            const uint32_t ab = st + (uint32_t)arow * ROWB + (uint32_t)ahalf * 32;
            uint32_t h0, h1, l0, l1, h2, h3, l2, l3;
            split4(areg[0], h0, h1, l0, l1);
            split4(areg[1], h2, h3, l2, l3);
            sts128(ab + STG_AH, h0, h1, h2, h3);
            sts128(ab + STG_AL, l0, l1, l2, l3);
            split4(areg[2], h0, h1, l0, l1);
            split4(areg[3], h2, h3, l2, l3);
            sts128(ab + STG_AH + 16, h0, h1, h2, h3);
            sts128(ab + STG_AL + 16, l0, l1, l2, l3);

            const uint32_t bb0 = st + (uint32_t)brow * ROWB + (uint32_t)bc * 16;
            const uint32_t bb1 = st + (uint32_t)(brow + 64) * ROWB + (uint32_t)bc * 16;
            sts128(bb0 + STG_BH, bh0.x, bh0.y, bh0.z, bh0.w);
            sts128(bb1 + STG_BH, bh1.x, bh1.y, bh1.z, bh1.w);
            sts128(bb0 + STG_BL, bl0.x, bl0.y, bl0.z, bl0.w);
            sts128(bb1 + STG_BL, bl1.x, bl1.y, bl1.z, bl1.w);
        }

        // 2. barrier: stage visible; also guarantees stage-s reads of it-2 done
        __syncthreads();

        // 3. prefetch next chunk into regs (overlaps with compute below)
        if (it + 1 < NITER) load_regs(it + 1);

        // 4. compute on stage s
        #pragma unroll
        for (int ks = 0; ks < 2; ks++) {
            const uint32_t cb = (uint32_t)ks * 32;  // byte col base (16 bf16)
            uint32_t ah[4][4], al[4][4], bhf[2][4], blf[2][4];
            #pragma unroll
            for (int mi = 0; mi < 4; mi++) {
                const uint32_t ra = st + (uint32_t)(wm * 64 + mi * 16 + lrow) * ROWB + cb + lcolh;
                ldmx4(ah[mi][0], ah[mi][1], ah[mi][2], ah[mi][3], ra + STG_AH);
                ldmx4(al[mi][0], al[mi][1], al[mi][2], al[mi][3], ra + STG_AL);
            }
            #pragma unroll
            for (int p = 0; p < 2; p++) {
                const uint32_t rb = st + (uint32_t)(wn * 32 + p * 16 + lrow) * ROWB + cb + lcolh;
                ldmx4(bhf[p][0], bhf[p][1], bhf[p][2], bhf[p][3], rb + STG_BH);
                ldmx4(blf[p][0], blf[p][1], blf[p][2], blf[p][3], rb + STG_BL);
            }
            // B ldmatrix regs: r0=n0-7/k0-7, r1=n8-15/k0-7, r2=n0-7/k8-15, r3=n8-15/k8-15
            #pragma unroll
            for (int mi = 0; mi < 4; mi++) {
                #pragma unroll
                for (int p = 0; p < 2; p++) {
                    // hh
                    mma16816(acc[mi][2*p][0], acc[mi][2*p][1], acc[mi][2*p][2], acc[mi][2*p][3],
                             ah[mi][0], ah[mi][1], ah[mi][2], ah[mi][3], bhf[p][0], bhf[p][2]);
                    mma16816(acc[mi][2*p+1][0], acc[mi][2*p+1][1], acc[mi][2*p+1][2], acc[mi][2*p+1][3],
                             ah[mi][0], ah[mi][1], ah[mi][2], ah[mi][3], bhf[p][1], bhf[p][3]);
                    // hl
                    mma16816(acc[mi][2*p][0], acc[mi][2*p][1], acc[mi][2*p][2], acc[mi][2*p][3],
                             ah[mi][0], ah[mi][1], ah[mi][2], ah[mi][3], blf[p][0], blf[p][2]);
                    mma16816(acc[mi][2*p+1][0], acc[mi][2*p+1][1], acc[mi][2*p+1][2], acc[mi][2*p+1][3],
                             ah[mi][0], ah[mi][1], ah[mi][2], ah[mi][3], blf[p][1], blf[p][3]);
                    // lh
                    mma16816(acc[mi][2*p][0], acc[mi][2*p][1], acc[mi][2*p][2], acc[mi][2*p][3],
                             al[mi][0], al[mi][1], al[mi][2], al[mi][3], bhf[p][0], bhf[p][2]);
                    mma16816(acc[mi][2*p+1][0], acc[mi][2*p+1][1], acc[mi][2*p+1][2], acc[mi][2*p+1][3],
                             al[mi][0], al[mi][1], al[mi][2], al[mi][3], bhf[p][1], bhf[p][3]);
                }
            }
        }
    }

    // ---- epilogue: acc -> global with bias ----
    const int gid = lid >> 2;       // 0..7
    const int tig = lid & 3;        // 0..3
    #pragma unroll
    for (int mi = 0; mi < 4; mi++) {
        const int r0 = m0 + wm * 64 + mi * 16 + gid;
        #pragma unroll
        for (int ni = 0; ni < 4; ni++) {
            const int c = n0 + wn * 32 + ni * 8 + tig * 2;
            const float2 bb = *(const float2*)(bias + c);
            float2 v0 = { acc[mi][ni][0] + bb.x, acc[mi][ni][1] + bb.y };
            float2 v1 = { acc[mi][ni][2] + bb.x, acc[mi][ni][3] + bb.y };
            *(float2*)(out + (size_t)r0 * NO + c) = v0;
            *(float2*)(out + (size_t)(r0 + 8) * NO + c) = v1;
        }
    }
}

// ===========================================================================
extern "C" void kernel_launch(void* const* d_in, const int* in_sizes, int n_in,
                              void* d_out, int out_size)
{
    (void)in_sizes; (void)n_in; (void)out_size;
    const void*  feat = d_in[0];
    const float* emb  = (const float*)d_in[1];
    const float* w    = (const float*)d_in[2];
    const float* bias = (const float*)d_in[3];
    float* out = (float*)d_out;

    k_init_flag<<<1, 32>>>();
    {
        const int half = BSZ * N_NODES / 2;
        k_detect<<<(half + 255) / 256, 256>>>((const unsigned long long*)feat);
    }
    k_convert<<<(BSZ * N_NODES + 255) / 256, 256>>>(feat);
    k_splitw<<<(NO * KDIM + 255) / 256, 256>>>(w);

    // idempotent, not a stream op (capture-safe); no static guard per harness rules
    cudaFuncSetAttribute(k_gemm, cudaFuncAttributeMaxDynamicSharedMemorySize, SMEM_ALLOC);

    dim3 grid(NO / BN, BSZ / BM);   // (4, 128)
    k_gemm<<<grid, THREADS, SMEM_ALLOC>>>(emb, bias, out);
}

// round 9
// speedup vs baseline: 2.2625x; 1.1322x over previous
#include <cuda_runtime.h>
#include <cuda_fp16.h>
#include <cstdint>
#include <cstddef>

#define N_NODES 19
#define NI      128
#define NO      512
#define KDIM    2432
#define BSZ     16384
#define VOCAB   20000

#define BM      128
#define BN      128
#define BK      32                 // fp16 k-chunk
#define NITER   (KDIM / BK)        // 76
#define THREADS 256

// ---- dynamic smem layout ----
#define ROWB        80                      // row pitch: 64B data + 16B pad (16B-aligned!)
#define OFF_IDX     0                       // 19*128*4 = 9728 B
#define OFF_STAGE   10240
#define STG_A       0                       // 128*80 = 10240 B
#define STG_BH      10240
#define STG_BL      20480
#define STAGE_BYTES 30720
#define SMEM_ALLOC  (OFF_STAGE + 2 * STAGE_BYTES)   // 71680

// ---- global scratch ----
__device__ int g_idx32[BSZ * N_NODES];
__device__ int g_is64;
__device__ __align__(16) __half g_whi[NO * KDIM];
__device__ __align__(16) __half g_wlo[NO * KDIM];

// ===========================================================================
// helpers
// ===========================================================================
__device__ __forceinline__ void sts128(uint32_t addr, uint32_t a, uint32_t b,
                                       uint32_t c, uint32_t d) {
    asm volatile("st.shared.v4.b32 [%0], {%1,%2,%3,%4};"
                 :: "r"(addr), "r"(a), "r"(b), "r"(c), "r"(d));
}

__device__ __forceinline__ void ldmx4(uint32_t& r0, uint32_t& r1, uint32_t& r2,
                                      uint32_t& r3, uint32_t addr) {
    asm volatile("ldmatrix.sync.aligned.m8n8.x4.shared.b16 {%0,%1,%2,%3}, [%4];"
                 : "=r"(r0), "=r"(r1), "=r"(r2), "=r"(r3) : "r"(addr));
}

__device__ __forceinline__ void mma16816(float& d0, float& d1, float& d2, float& d3,
                                         uint32_t a0, uint32_t a1, uint32_t a2, uint32_t a3,
                                         uint32_t b0, uint32_t b1) {
    asm volatile("mma.sync.aligned.m16n8k16.row.col.f32.f16.f16.f32 "
                 "{%0,%1,%2,%3}, {%4,%5,%6,%7}, {%8,%9}, {%0,%1,%2,%3};"
                 : "+f"(d0), "+f"(d1), "+f"(d2), "+f"(d3)
                 : "r"(a0), "r"(a1), "r"(a2), "r"(a3), "r"(b0), "r"(b1));
}

__device__ __forceinline__ uint32_t pack_h2(float x, float y) {
    __half2 h = __floats2half2_rn(x, y);
    return *reinterpret_cast<uint32_t*>(&h);
}

// ===========================================================================
// prologue kernels
// ===========================================================================
__global__ void k_init_flag() { if (threadIdx.x == 0) g_is64 = 1; }

__global__ void k_detect(const unsigned long long* __restrict__ f) {
    const int half = BSZ * N_NODES / 2;
    int i = blockIdx.x * blockDim.x + threadIdx.x;
    if (i < half && f[i] >= (unsigned long long)VOCAB) g_is64 = 0;
}

__global__ void k_convert(const void* __restrict__ f) {
    int i = blockIdx.x * blockDim.x + threadIdx.x;
    if (i < BSZ * N_NODES) {
        g_idx32[i] = g_is64 ? (int)((const long long*)f)[i] : ((const int*)f)[i];
    }
}

// W -> fp16 hi + fp16 lo (residual)
__global__ void k_splitw(const float* __restrict__ w) {
    int i = blockIdx.x * blockDim.x + threadIdx.x;
    if (i < NO * KDIM) {
        float v = w[i];
        __half h = __float2half_rn(v);
        g_whi[i] = h;
        g_wlo[i] = __float2half_rn(v - __half2float(h));
    }
}

// ===========================================================================
// fused gather + fp16 2-pass HMMA GEMM
//   out = A_f16 * (B_hi + B_lo)^T + bias, fp32 accumulate
// ===========================================================================
__global__ __launch_bounds__(THREADS, 1)
void k_gemm(const float* __restrict__ emb, const float* __restrict__ bias,
            float* __restrict__ out)
{
    extern __shared__ char smem[];
    const uint32_t sb = (uint32_t)__cvta_generic_to_shared(smem);

    const int tid = threadIdx.x;
    const int wid = tid >> 5;
    const int lid = tid & 31;
    const int m0 = blockIdx.y * BM;
    const int n0 = blockIdx.x * BN;
    const int wm = wid >> 2;       // 0..1 -> warp m block (64 rows)
    const int wn = wid & 3;        // 0..3 -> warp n block (32 cols)

    // stage gather indices: idxS[node][row]
    int* idxS = (int*)(smem + OFF_IDX);
    for (int i = tid; i < N_NODES * BM; i += THREADS) {
        int node = i >> 7, r = i & 127;
        idxS[node * BM + r] = g_idx32[(m0 + r) * N_NODES + node];
    }
    __syncthreads();

    // ---- producer roles ----
    const int arow = tid & 127;    // A: 2 threads/row, 16 fp32 -> 16 fp16 (32B) each
    const int ahalf = tid >> 7;
    const int brow = tid >> 1;     // B: 2 threads/row, 32B hi + 32B lo each
    const int psel = tid & 1;

    float4 areg[4];
    uint4  bh0, bh1, bl0, bl1;

    auto load_regs = [&](int it) {
        const int k0 = it * BK;
        const int node = k0 >> 7;
        const float* ap = emb +
            ((size_t)node * VOCAB + idxS[node * BM + arow]) * NI + (k0 & 127) + ahalf * 16;
        #pragma unroll
        for (int i = 0; i < 4; i++) areg[i] = ((const float4*)ap)[i];
        const size_t bo = (size_t)(n0 + brow) * KDIM + k0 + psel * 16;
        bh0 = ((const uint4*)(g_whi + bo))[0];
        bh1 = ((const uint4*)(g_whi + bo))[1];
        bl0 = ((const uint4*)(g_wlo + bo))[0];
        bl1 = ((const uint4*)(g_wlo + bo))[1];
    };

    float acc[4][4][4];
    #pragma unroll
    for (int i = 0; i < 4; i++)
        #pragma unroll
        for (int j = 0; j < 4; j++)
            #pragma unroll
            for (int q = 0; q < 4; q++)
                acc[i][j][q] = 0.0f;

    load_regs(0);

    const uint32_t lrow = (uint32_t)(lid & 15);
    const uint32_t lcolh = (uint32_t)((lid >> 4) * 16);

    for (int it = 0; it < NITER; it++) {
        const uint32_t st = sb + OFF_STAGE + (uint32_t)(it & 1) * STAGE_BYTES;

        // 1. STS staged registers -> smem (A converted fp32->fp16 here)
        {
            const uint32_t ab = st + STG_A + (uint32_t)arow * ROWB + (uint32_t)ahalf * 32;
            uint32_t p0 = pack_h2(areg[0].x, areg[0].y);
            uint32_t p1 = pack_h2(areg[0].z, areg[0].w);
            uint32_t p2 = pack_h2(areg[1].x, areg[1].y);
            uint32_t p3 = pack_h2(areg[1].z, areg[1].w);
            sts128(ab, p0, p1, p2, p3);
            p0 = pack_h2(areg[2].x, areg[2].y);
            p1 = pack_h2(areg[2].z, areg[2].w);
            p2 = pack_h2(areg[3].x, areg[3].y);
            p3 = pack_h2(areg[3].z, areg[3].w);
            sts128(ab + 16, p0, p1, p2, p3);

            const uint32_t bb = st + (uint32_t)brow * ROWB + (uint32_t)psel * 32;
            sts128(bb + STG_BH,      bh0.x, bh0.y, bh0.z, bh0.w);
            sts128(bb + STG_BH + 16, bh1.x, bh1.y, bh1.z, bh1.w);
            sts128(bb + STG_BL,      bl0.x, bl0.y, bl0.z, bl0.w);
            sts128(bb + STG_BL + 16, bl1.x, bl1.y, bl1.z, bl1.w);
        }

        // 2. barrier: stage visible; all threads done reading slot (it-1)&1
        __syncthreads();

        // 3. prefetch next chunk (overlaps with compute)
        if (it + 1 < NITER) load_regs(it + 1);

        // 4. compute on stage s
        #pragma unroll
        for (int ks = 0; ks < 2; ks++) {
            const uint32_t cb = (uint32_t)ks * 32;
            uint32_t ah[4][4], bhf[2][4], blf[2][4];
            #pragma unroll
            for (int mi = 0; mi < 4; mi++) {
                const uint32_t ra = st + STG_A +
                    (uint32_t)(wm * 64 + mi * 16 + lrow) * ROWB + cb + lcolh;
                ldmx4(ah[mi][0], ah[mi][1], ah[mi][2], ah[mi][3], ra);
            }
            #pragma unroll
            for (int p = 0; p < 2; p++) {
                const uint32_t rb = st +
                    (uint32_t)(wn * 32 + p * 16 + lrow) * ROWB + cb + lcolh;
                ldmx4(bhf[p][0], bhf[p][1], bhf[p][2], bhf[p][3], rb + STG_BH);
                ldmx4(blf[p][0], blf[p][1], blf[p][2], blf[p][3], rb + STG_BL);
            }
            #pragma unroll
            for (int mi = 0; mi < 4; mi++) {
                #pragma unroll
                for (int p = 0; p < 2; p++) {
                    // hi pass
                    mma16816(acc[mi][2*p][0], acc[mi][2*p][1], acc[mi][2*p][2], acc[mi][2*p][3],
                             ah[mi][0], ah[mi][1], ah[mi][2], ah[mi][3], bhf[p][0], bhf[p][2]);
                    mma16816(acc[mi][2*p+1][0], acc[mi][2*p+1][1], acc[mi][2*p+1][2], acc[mi][2*p+1][3],
                             ah[mi][0], ah[mi][1], ah[mi][2], ah[mi][3], bhf[p][1], bhf[p][3]);
                    // lo pass
                    mma16816(acc[mi][2*p][0], acc[mi][2*p][1], acc[mi][2*p][2], acc[mi][2*p][3],
                             ah[mi][0], ah[mi][1], ah[mi][2], ah[mi][3], blf[p][0], blf[p][2]);
                    mma16816(acc[mi][2*p+1][0], acc[mi][2*p+1][1], acc[mi][2*p+1][2], acc[mi][2*p+1][3],
                             ah[mi][0], ah[mi][1], ah[mi][2], ah[mi][3], blf[p][1], blf[p][3]);
                }
            }
        }
    }

    // ---- epilogue: acc -> global with bias ----
    const int gid = lid >> 2;
    const int tig = lid & 3;
    #pragma unroll
    for (int mi = 0; mi < 4; mi++) {
        const int r0 = m0 + wm * 64 + mi * 16 + gid;
        #pragma unroll
        for (int ni = 0; ni < 4; ni++) {
            const int c = n0 + wn * 32 + ni * 8 + tig * 2;
            const float2 bb = *(const float2*)(bias + c);
            float2 v0 = { acc[mi][ni][0] + bb.x, acc[mi][ni][1] + bb.y };
            float2 v1 = { acc[mi][ni][2] + bb.x, acc[mi][ni][3] + bb.y };
            *(float2*)(out + (size_t)r0 * NO + c) = v0;
            *(float2*)(out + (size_t)(r0 + 8) * NO + c) = v1;
        }
    }
}

// ===========================================================================
extern "C" void kernel_launch(void* const* d_in, const int* in_sizes, int n_in,
                              void* d_out, int out_size)
{
    (void)in_sizes; (void)n_in; (void)out_size;
    const void*  feat = d_in[0];
    const float* emb  = (const float*)d_in[1];
    const float* w    = (const float*)d_in[2];
    const float* bias = (const float*)d_in[3];
    float* out = (float*)d_out;

    k_init_flag<<<1, 32>>>();
    {
        const int half = BSZ * N_NODES / 2;
        k_detect<<<(half + 255) / 256, 256>>>((const unsigned long long*)feat);
    }
    k_convert<<<(BSZ * N_NODES + 255) / 256, 256>>>(feat);
    k_splitw<<<(NO * KDIM + 255) / 256, 256>>>(w);

    cudaFuncSetAttribute(k_gemm, cudaFuncAttributeMaxDynamicSharedMemorySize, SMEM_ALLOC);

    dim3 grid(NO / BN, BSZ / BM);   // (4, 128)
    k_gemm<<<grid, THREADS, SMEM_ALLOC>>>(emb, bias, out);
}

// round 11
// speedup vs baseline: 2.7728x; 1.2256x over previous
#include <cuda_runtime.h>
#include <cuda_fp16.h>
#include <cstdint>
#include <cstddef>

#define N_NODES 19
#define NI      128
#define NO      512
#define KDIM    2432
#define BSZ     16384
#define VOCAB   20000

#define BM      128
#define BN      128
#define BK      32                 // fp16 k-chunk
#define NITER   (KDIM / BK)        // 76
#define THREADS 256

// ---- dynamic smem layout ----
#define ROWB        80                      // row pitch: 64B data + 16B pad (16B-aligned)
#define OFF_IDX     0                       // 19*128*4 = 9728 B
#define OFF_STAGE   10240
#define STG_A       0                       // 128*80 = 10240 B
#define STG_BH      10240
#define STG_BL      20480
#define STAGE_BYTES 30720
#define SMEM_ALLOC  (OFF_STAGE + 2 * STAGE_BYTES)   // 71680  (x2 CTAs = 143KB/SM)

// ---- global scratch ----
__device__ int g_idx32[BSZ * N_NODES];
__device__ int g_is64;
__device__ __align__(16) __half g_whi[NO * KDIM];
__device__ __align__(16) __half g_wlo[NO * KDIM];

// ===========================================================================
// helpers
// ===========================================================================
__device__ __forceinline__ void cpa16(uint32_t dst, const void* src) {
    asm volatile("cp.async.cg.shared.global [%0], [%1], 16;"
                 :: "r"(dst), "l"(src) : "memory");
}
__device__ __forceinline__ void cpa_commit() {
    asm volatile("cp.async.commit_group;" ::: "memory");
}
__device__ __forceinline__ void cpa_wait_all() {
    asm volatile("cp.async.wait_group 0;" ::: "memory");
}

__device__ __forceinline__ void sts128(uint32_t addr, uint32_t a, uint32_t b,
                                       uint32_t c, uint32_t d) {
    asm volatile("st.shared.v4.b32 [%0], {%1,%2,%3,%4};"
                 :: "r"(addr), "r"(a), "r"(b), "r"(c), "r"(d));
}

__device__ __forceinline__ void ldmx4(uint32_t& r0, uint32_t& r1, uint32_t& r2,
                                      uint32_t& r3, uint32_t addr) {
    asm volatile("ldmatrix.sync.aligned.m8n8.x4.shared.b16 {%0,%1,%2,%3}, [%4];"
                 : "=r"(r0), "=r"(r1), "=r"(r2), "=r"(r3) : "r"(addr));
}

__device__ __forceinline__ void mma16816(float& d0, float& d1, float& d2, float& d3,
                                         uint32_t a0, uint32_t a1, uint32_t a2, uint32_t a3,
                                         uint32_t b0, uint32_t b1) {
    asm volatile("mma.sync.aligned.m16n8k16.row.col.f32.f16.f16.f32 "
                 "{%0,%1,%2,%3}, {%4,%5,%6,%7}, {%8,%9}, {%0,%1,%2,%3};"
                 : "+f"(d0), "+f"(d1), "+f"(d2), "+f"(d3)
                 : "r"(a0), "r"(a1), "r"(a2), "r"(a3), "r"(b0), "r"(b1));
}

__device__ __forceinline__ uint32_t pack_h2(float x, float y) {
    __half2 h = __floats2half2_rn(x, y);
    return *reinterpret_cast<uint32_t*>(&h);
}

// ===========================================================================
// prologue kernels
// ===========================================================================
__global__ void k_init_flag() { if (threadIdx.x == 0) g_is64 = 1; }

__global__ void k_detect(const unsigned long long* __restrict__ f) {
    const int half = BSZ * N_NODES / 2;
    int i = blockIdx.x * blockDim.x + threadIdx.x;
    if (i < half && f[i] >= (unsigned long long)VOCAB) g_is64 = 0;
}

__global__ void k_convert(const void* __restrict__ f) {
    int i = blockIdx.x * blockDim.x + threadIdx.x;
    if (i < BSZ * N_NODES) {
        g_idx32[i] = g_is64 ? (int)((const long long*)f)[i] : ((const int*)f)[i];
    }
}

// W -> fp16 hi + fp16 lo (residual)
__global__ void k_splitw(const float* __restrict__ w) {
    int i = blockIdx.x * blockDim.x + threadIdx.x;
    if (i < NO * KDIM) {
        float v = w[i];
        __half h = __float2half_rn(v);
        g_whi[i] = h;
        g_wlo[i] = __float2half_rn(v - __half2float(h));
    }
}

// ===========================================================================
// fused gather + fp16 2-pass HMMA GEMM
//   A: gathered fp32 -> fp16 via registers; B: cp.async direct from g_whi/g_wlo
// ===========================================================================
__global__ __launch_bounds__(THREADS, 2)
void k_gemm(const float* __restrict__ emb, const float* __restrict__ bias,
            float* __restrict__ out)
{
    extern __shared__ char smem[];
    const uint32_t sb = (uint32_t)__cvta_generic_to_shared(smem);

    const int tid = threadIdx.x;
    const int wid = tid >> 5;
    const int lid = tid & 31;
    const int m0 = blockIdx.y * BM;
    const int n0 = blockIdx.x * BN;
    const int wm = wid >> 2;       // 0..1 -> warp m block (64 rows)
    const int wn = wid & 3;        // 0..3 -> warp n block (32 cols)

    // stage gather indices: idxS[node][row]
    int* idxS = (int*)(smem + OFF_IDX);
    for (int i = tid; i < N_NODES * BM; i += THREADS) {
        int node = i >> 7, r = i & 127;
        idxS[node * BM + r] = g_idx32[(m0 + r) * N_NODES + node];
    }
    __syncthreads();

    // ---- producer roles ----
    const int arow = tid & 127;    // A: 2 threads/row, 16 fp32 -> 16 fp16 (32B) each
    const int ahalf = tid >> 7;
    const int brow = tid >> 1;     // B: 2 threads/row, 32B hi + 32B lo each
    const int psel = tid & 1;

    float4 areg[4];                // gathered A (16 fp32)

    auto load_A = [&](int it) {
        const int k0 = it * BK;
        const int node = k0 >> 7;
        const float* ap = emb +
            ((size_t)node * VOCAB + idxS[node * BM + arow]) * NI + (k0 & 127) + ahalf * 16;
        #pragma unroll
        for (int i = 0; i < 4; i++) areg[i] = ((const float4*)ap)[i];
    };

    auto issue_B = [&](int it) {
        if (it < NITER) {
            const uint32_t st2 = sb + OFF_STAGE + (uint32_t)(it & 1) * STAGE_BYTES;
            const size_t bo = (size_t)(n0 + brow) * KDIM + it * BK + psel * 16;
            const uint32_t bb = st2 + (uint32_t)brow * ROWB + (uint32_t)psel * 32;
            cpa16(bb + STG_BH,      g_whi + bo);
            cpa16(bb + STG_BH + 16, g_whi + bo + 8);
            cpa16(bb + STG_BL,      g_wlo + bo);
            cpa16(bb + STG_BL + 16, g_wlo + bo + 8);
            cpa_commit();
        }
    };

    float acc[4][4][4];
    #pragma unroll
    for (int i = 0; i < 4; i++)
        #pragma unroll
        for (int j = 0; j < 4; j++)
            #pragma unroll
            for (int q = 0; q < 4; q++)
                acc[i][j][q] = 0.0f;

    issue_B(0);
    load_A(0);

    const uint32_t lrow = (uint32_t)(lid & 15);
    const uint32_t lcolh = (uint32_t)((lid >> 4) * 16);

    for (int it = 0; it < NITER; it++) {
        const uint32_t st = sb + OFF_STAGE + (uint32_t)(it & 1) * STAGE_BYTES;

        // 1. STS A(it) -> stage s (safe: all threads passed barrier(it-1), so all
        //    finished reading s at compute(it-2))
        {
            const uint32_t ab = st + STG_A + (uint32_t)arow * ROWB + (uint32_t)ahalf * 32;
            uint32_t p0 = pack_h2(areg[0].x, areg[0].y);
            uint32_t p1 = pack_h2(areg[0].z, areg[0].w);
            uint32_t p2 = pack_h2(areg[1].x, areg[1].y);
            uint32_t p3 = pack_h2(areg[1].z, areg[1].w);
            sts128(ab, p0, p1, p2, p3);
            p0 = pack_h2(areg[2].x, areg[2].y);
            p1 = pack_h2(areg[2].z, areg[2].w);
            p2 = pack_h2(areg[3].x, areg[3].y);
            p3 = pack_h2(areg[3].z, areg[3].w);
            sts128(ab + 16, p0, p1, p2, p3);
        }

        // 2. B(it) landed (issued one compute-phase ago -> latency hidden)
        cpa_wait_all();

        // 3. barrier: A-STS + this thread's cp.async visible; all compute(it-1) done
        __syncthreads();

        // 4. refill: B(it+1) into s^1 (safe post-barrier), prefetch A(it+1) regs
        issue_B(it + 1);
        if (it + 1 < NITER) load_A(it + 1);

        // 5. compute on stage s
        #pragma unroll
        for (int ks = 0; ks < 2; ks++) {
            const uint32_t cb = (uint32_t)ks * 32;
            uint32_t ah[4][4], bhf[2][4], blf[2][4];
            #pragma unroll
            for (int mi = 0; mi < 4; mi++) {
                const uint32_t ra = st + STG_A +
                    (uint32_t)(wm * 64 + mi * 16 + lrow) * ROWB + cb + lcolh;
                ldmx4(ah[mi][0], ah[mi][1], ah[mi][2], ah[mi][3], ra);
            }
            #pragma unroll
            for (int p = 0; p < 2; p++) {
                const uint32_t rb = st +
                    (uint32_t)(wn * 32 + p * 16 + lrow) * ROWB + cb + lcolh;
                ldmx4(bhf[p][0], bhf[p][1], bhf[p][2], bhf[p][3], rb + STG_BH);
                ldmx4(blf[p][0], blf[p][1], blf[p][2], blf[p][3], rb + STG_BL);
            }
            #pragma unroll
            for (int mi = 0; mi < 4; mi++) {
                #pragma unroll
                for (int p = 0; p < 2; p++) {
                    // hi pass
                    mma16816(acc[mi][2*p][0], acc[mi][2*p][1], acc[mi][2*p][2], acc[mi][2*p][3],
                             ah[mi][0], ah[mi][1], ah[mi][2], ah[mi][3], bhf[p][0], bhf[p][2]);
                    mma16816(acc[mi][2*p+1][0], acc[mi][2*p+1][1], acc[mi][2*p+1][2], acc[mi][2*p+1][3],
                             ah[mi][0], ah[mi][1], ah[mi][2], ah[mi][3], bhf[p][1], bhf[p][3]);
                    // lo pass
                    mma16816(acc[mi][2*p][0], acc[mi][2*p][1], acc[mi][2*p][2], acc[mi][2*p][3],
                             ah[mi][0], ah[mi][1], ah[mi][2], ah[mi][3], blf[p][0], blf[p][2]);
                    mma16816(acc[mi][2*p+1][0], acc[mi][2*p+1][1], acc[mi][2*p+1][2], acc[mi][2*p+1][3],
                             ah[mi][0], ah[mi][1], ah[mi][2], ah[mi][3], blf[p][1], blf[p][3]);
                }
            }
        }
    }

    // ---- epilogue: acc -> global with bias ----
    const int gid = lid >> 2;
    const int tig = lid & 3;
    #pragma unroll
    for (int mi = 0; mi < 4; mi++) {
        const int r0 = m0 + wm * 64 + mi * 16 + gid;
        #pragma unroll
        for (int ni = 0; ni < 4; ni++) {
            const int c = n0 + wn * 32 + ni * 8 + tig * 2;
            const float2 bb = *(const float2*)(bias + c);
            float2 v0 = { acc[mi][ni][0] + bb.x, acc[mi][ni][1] + bb.y };
            float2 v1 = { acc[mi][ni][2] + bb.x, acc[mi][ni][3] + bb.y };
            *(float2*)(out + (size_t)r0 * NO + c) = v0;
            *(float2*)(out + (size_t)(r0 + 8) * NO + c) = v1;
        }
    }
}

// ===========================================================================
extern "C" void kernel_launch(void* const* d_in, const int* in_sizes, int n_in,
                              void* d_out, int out_size)
{
    (void)in_sizes; (void)n_in; (void)out_size;
    const void*  feat = d_in[0];
    const float* emb  = (const float*)d_in[1];
    const float* w    = (const float*)d_in[2];
    const float* bias = (const float*)d_in[3];
    float* out = (float*)d_out;

    k_init_flag<<<1, 32>>>();
    {
        const int half = BSZ * N_NODES / 2;
        k_detect<<<(half + 255) / 256, 256>>>((const unsigned long long*)feat);
    }
    k_convert<<<(BSZ * N_NODES + 255) / 256, 256>>>(feat);
    k_splitw<<<(NO * KDIM + 255) / 256, 256>>>(w);

    cudaFuncSetAttribute(k_gemm, cudaFuncAttributeMaxDynamicSharedMemorySize, SMEM_ALLOC);

    dim3 grid(NO / BN, BSZ / BM);   // (4, 128)
    k_gemm<<<grid, THREADS, SMEM_ALLOC>>>(emb, bias, out);
}

// round 12
// speedup vs baseline: 3.5805x; 1.2913x over previous
#include <cuda_runtime.h>
#include <cuda_fp16.h>
#include <cstdint>
#include <cstddef>

#define N_NODES 19
#define NI      128
#define NO      512
#define KDIM    2432
#define BSZ     16384
#define VOCAB   20000

#define BM      128
#define BN      128
#define BK      32                 // fp16 k-chunk
#define NITER   (KDIM / BK)        // 76
#define THREADS 256

// ---- dynamic smem layout ----
#define ROWB        80                      // row pitch: 64B data + 16B pad (16B-aligned)
#define OFF_IDX     0                       // 19*128*4 = 9728 B
#define OFF_STAGE   10240
#define STG_A       0                       // 128*80 = 10240 B
#define STG_BH      10240
#define STAGE_BYTES 20480
#define SMEM_ALLOC  (OFF_STAGE + 2 * STAGE_BYTES)   // 51200  (x2 CTAs = 102KB/SM)

// ---- global scratch ----
__device__ int g_idx32[BSZ * N_NODES];
__device__ int g_is64;
__device__ __align__(16) __half g_whi[NO * KDIM];

// ===========================================================================
// helpers
// ===========================================================================
__device__ __forceinline__ void cpa16(uint32_t dst, const void* src) {
    asm volatile("cp.async.cg.shared.global [%0], [%1], 16;"
                 :: "r"(dst), "l"(src) : "memory");
}
__device__ __forceinline__ void cpa_commit() {
    asm volatile("cp.async.commit_group;" ::: "memory");
}
__device__ __forceinline__ void cpa_wait_all() {
    asm volatile("cp.async.wait_group 0;" ::: "memory");
}

__device__ __forceinline__ void sts128(uint32_t addr, uint32_t a, uint32_t b,
                                       uint32_t c, uint32_t d) {
    asm volatile("st.shared.v4.b32 [%0], {%1,%2,%3,%4};"
                 :: "r"(addr), "r"(a), "r"(b), "r"(c), "r"(d));
}

__device__ __forceinline__ void ldmx4(uint32_t& r0, uint32_t& r1, uint32_t& r2,
                                      uint32_t& r3, uint32_t addr) {
    asm volatile("ldmatrix.sync.aligned.m8n8.x4.shared.b16 {%0,%1,%2,%3}, [%4];"
                 : "=r"(r0), "=r"(r1), "=r"(r2), "=r"(r3) : "r"(addr));
}

__device__ __forceinline__ void mma16816(float& d0, float& d1, float& d2, float& d3,
                                         uint32_t a0, uint32_t a1, uint32_t a2, uint32_t a3,
                                         uint32_t b0, uint32_t b1) {
    asm volatile("mma.sync.aligned.m16n8k16.row.col.f32.f16.f16.f32 "
                 "{%0,%1,%2,%3}, {%4,%5,%6,%7}, {%8,%9}, {%0,%1,%2,%3};"
                 : "+f"(d0), "+f"(d1), "+f"(d2), "+f"(d3)
                 : "r"(a0), "r"(a1), "r"(a2), "r"(a3), "r"(b0), "r"(b1));
}

__device__ __forceinline__ uint32_t pack_h2(float x, float y) {
    __half2 h = __floats2half2_rn(x, y);
    return *reinterpret_cast<uint32_t*>(&h);
}

// ===========================================================================
// prologue kernels
// ===========================================================================
__global__ void k_init_flag() { if (threadIdx.x == 0) g_is64 = 1; }

__global__ void k_detect(const unsigned long long* __restrict__ f) {
    const int half = BSZ * N_NODES / 2;
    int i = blockIdx.x * blockDim.x + threadIdx.x;
    if (i < half && f[i] >= (unsigned long long)VOCAB) g_is64 = 0;
}

__global__ void k_convert(const void* __restrict__ f) {
    int i = blockIdx.x * blockDim.x + threadIdx.x;
    if (i < BSZ * N_NODES) {
        g_idx32[i] = g_is64 ? (int)((const long long*)f)[i] : ((const int*)f)[i];
    }
}

// W -> fp16
__global__ void k_cvtw(const float* __restrict__ w) {
    int i = blockIdx.x * blockDim.x + threadIdx.x;
    if (i < NO * KDIM) g_whi[i] = __float2half_rn(w[i]);
}

// ===========================================================================
// fused gather + fp16 HMMA GEMM (single pass, fp32 accumulate)
//   A: gathered fp32 -> fp16 via registers; B: cp.async direct from g_whi
// ===========================================================================
__global__ __launch_bounds__(THREADS, 2)
void k_gemm(const float* __restrict__ emb, const float* __restrict__ bias,
            float* __restrict__ out)
{
    extern __shared__ char smem[];
    const uint32_t sb = (uint32_t)__cvta_generic_to_shared(smem);

    const int tid = threadIdx.x;
    const int wid = tid >> 5;
    const int lid = tid & 31;
    const int m0 = blockIdx.y * BM;
    const int n0 = blockIdx.x * BN;
    const int wm = wid >> 2;       // 0..1 -> warp m block (64 rows)
    const int wn = wid & 3;        // 0..3 -> warp n block (32 cols)

    // stage gather indices: idxS[node][row]
    int* idxS = (int*)(smem + OFF_IDX);
    for (int i = tid; i < N_NODES * BM; i += THREADS) {
        int node = i >> 7, r = i & 127;
        idxS[node * BM + r] = g_idx32[(m0 + r) * N_NODES + node];
    }
    __syncthreads();

    // ---- producer roles ----
    const int arow = tid & 127;    // A: 2 threads/row, 16 fp32 -> 16 fp16 (32B) each
    const int ahalf = tid >> 7;
    const int brow = tid >> 1;     // B: 2 threads/row, 32B each
    const int psel = tid & 1;

    float4 areg[4];                // gathered A (16 fp32)

    auto load_A = [&](int it) {
        const int k0 = it * BK;
        const int node = k0 >> 7;
        const float* ap = emb +
            ((size_t)node * VOCAB + idxS[node * BM + arow]) * NI + (k0 & 127) + ahalf * 16;
        #pragma unroll
        for (int i = 0; i < 4; i++) areg[i] = ((const float4*)ap)[i];
    };

    auto issue_B = [&](int it) {
        if (it < NITER) {
            const uint32_t st2 = sb + OFF_STAGE + (uint32_t)(it & 1) * STAGE_BYTES;
            const size_t bo = (size_t)(n0 + brow) * KDIM + it * BK + psel * 16;
            const uint32_t bb = st2 + STG_BH + (uint32_t)brow * ROWB + (uint32_t)psel * 32;
            cpa16(bb,      g_whi + bo);
            cpa16(bb + 16, g_whi + bo + 8);
            cpa_commit();
        }
    };

    float acc[4][4][4];
    #pragma unroll
    for (int i = 0; i < 4; i++)
        #pragma unroll
        for (int j = 0; j < 4; j++)
            #pragma unroll
            for (int q = 0; q < 4; q++)
                acc[i][j][q] = 0.0f;

    issue_B(0);
    load_A(0);

    const uint32_t lrow = (uint32_t)(lid & 15);
    const uint32_t lcolh = (uint32_t)((lid >> 4) * 16);

    for (int it = 0; it < NITER; it++) {
        const uint32_t st = sb + OFF_STAGE + (uint32_t)(it & 1) * STAGE_BYTES;

        // 1. STS A(it) -> stage s (all threads passed barrier(it-1): slot free)
        {
            const uint32_t ab = st + STG_A + (uint32_t)arow * ROWB + (uint32_t)ahalf * 32;
            uint32_t p0 = pack_h2(areg[0].x, areg[0].y);
            uint32_t p1 = pack_h2(areg[0].z, areg[0].w);
            uint32_t p2 = pack_h2(areg[1].x, areg[1].y);
            uint32_t p3 = pack_h2(areg[1].z, areg[1].w);
            sts128(ab, p0, p1, p2, p3);
            p0 = pack_h2(areg[2].x, areg[2].y);
            p1 = pack_h2(areg[2].z, areg[2].w);
            p2 = pack_h2(areg[3].x, areg[3].y);
            p3 = pack_h2(areg[3].z, areg[3].w);
            sts128(ab + 16, p0, p1, p2, p3);
        }

        // 2. B(it) landed (issued a full compute-phase earlier)
        cpa_wait_all();

        // 3. barrier: A-STS + cp.async visible; all compute(it-1) done
        __syncthreads();

        // 4. refill B(it+1) into s^1; prefetch A(it+1) regs
        issue_B(it + 1);
        if (it + 1 < NITER) load_A(it + 1);

        // 5. compute on stage s
        #pragma unroll
        for (int ks = 0; ks < 2; ks++) {
            const uint32_t cb = (uint32_t)ks * 32;
            uint32_t ah[4][4], bhf[2][4];
            #pragma unroll
            for (int mi = 0; mi < 4; mi++) {
                const uint32_t ra = st + STG_A +
                    (uint32_t)(wm * 64 + mi * 16 + lrow) * ROWB + cb + lcolh;
                ldmx4(ah[mi][0], ah[mi][1], ah[mi][2], ah[mi][3], ra);
            }
            #pragma unroll
            for (int p = 0; p < 2; p++) {
                const uint32_t rb = st + STG_BH +
                    (uint32_t)(wn * 32 + p * 16 + lrow) * ROWB + cb + lcolh;
                ldmx4(bhf[p][0], bhf[p][1], bhf[p][2], bhf[p][3], rb);
            }
            #pragma unroll
            for (int mi = 0; mi < 4; mi++) {
                #pragma unroll
                for (int p = 0; p < 2; p++) {
                    mma16816(acc[mi][2*p][0], acc[mi][2*p][1], acc[mi][2*p][2], acc[mi][2*p][3],
                             ah[mi][0], ah[mi][1], ah[mi][2], ah[mi][3], bhf[p][0], bhf[p][2]);
                    mma16816(acc[mi][2*p+1][0], acc[mi][2*p+1][1], acc[mi][2*p+1][2], acc[mi][2*p+1][3],
                             ah[mi][0], ah[mi][1], ah[mi][2], ah[mi][3], bhf[p][1], bhf[p][3]);
                }
            }
        }
    }

    // ---- epilogue: acc -> global with bias ----
    const int gid = lid >> 2;
    const int tig = lid & 3;
    #pragma unroll
    for (int mi = 0; mi < 4; mi++) {
        const int r0 = m0 + wm * 64 + mi * 16 + gid;
        #pragma unroll
        for (int ni = 0; ni < 4; ni++) {
            const int c = n0 + wn * 32 + ni * 8 + tig * 2;
            const float2 bb = *(const float2*)(bias + c);
            float2 v0 = { acc[mi][ni][0] + bb.x, acc[mi][ni][1] + bb.y };
            float2 v1 = { acc[mi][ni][2] + bb.x, acc[mi][ni][3] + bb.y };
            *(float2*)(out + (size_t)r0 * NO + c) = v0;
            *(float2*)(out + (size_t)(r0 + 8) * NO + c) = v1;
        }
    }
}

// ===========================================================================
extern "C" void kernel_launch(void* const* d_in, const int* in_sizes, int n_in,
                              void* d_out, int out_size)
{
    (void)in_sizes; (void)n_in; (void)out_size;
    const void*  feat = d_in[0];
    const float* emb  = (const float*)d_in[1];
    const float* w    = (const float*)d_in[2];
    const float* bias = (const float*)d_in[3];
    float* out = (float*)d_out;

    k_init_flag<<<1, 32>>>();
    {
        const int half = BSZ * N_NODES / 2;
        k_detect<<<(half + 255) / 256, 256>>>((const unsigned long long*)feat);
    }
    k_convert<<<(BSZ * N_NODES + 255) / 256, 256>>>(feat);
    k_cvtw<<<(NO * KDIM + 255) / 256, 256>>>(w);

    cudaFuncSetAttribute(k_gemm, cudaFuncAttributeMaxDynamicSharedMemorySize, SMEM_ALLOC);

    dim3 grid(NO / BN, BSZ / BM);   // (4, 128)
    k_gemm<<<grid, THREADS, SMEM_ALLOC>>>(emb, bias, out);
}

// round 13
// speedup vs baseline: 3.9835x; 1.1126x over previous
#include <cuda_runtime.h>
#include <cuda_fp16.h>
#include <cstdint>
#include <cstddef>

#define N_NODES 19
#define NI      128
#define NO      512
#define KDIM    2432
#define BSZ     16384
#define VOCAB   20000

#define BM      128
#define BN      128
#define BK      64                 // fp16 k-chunk
#define NITER   (KDIM / BK)        // 38
#define THREADS 256

// ---- dynamic smem layout ----
#define ROWB        144                     // 128B data + 16B pad (16B-aligned, conflict-free)
#define STG_A       0                       // 128*144 = 18432 B
#define STG_B       18432
#define STAGE_BYTES 36864
#define SMEM_ALLOC  (2 * STAGE_BYTES)       // 73728  (x2 CTAs = 147KB/SM)

// ---- global scratch ----
__device__ int g_idx32[BSZ * N_NODES];
__device__ int g_is64;
__device__ __align__(16) __half g_whi[NO * KDIM];
__device__ __align__(16) __half g_h[(size_t)BSZ * KDIM];   // gathered A, fp16 (76MB)

// ===========================================================================
// helpers
// ===========================================================================
__device__ __forceinline__ void cpa16(uint32_t dst, const void* src) {
    asm volatile("cp.async.cg.shared.global [%0], [%1], 16;"
                 :: "r"(dst), "l"(src) : "memory");
}
__device__ __forceinline__ void cpa_commit() {
    asm volatile("cp.async.commit_group;" ::: "memory");
}
__device__ __forceinline__ void cpa_wait_all() {
    asm volatile("cp.async.wait_group 0;" ::: "memory");
}

__device__ __forceinline__ void ldmx4(uint32_t& r0, uint32_t& r1, uint32_t& r2,
                                      uint32_t& r3, uint32_t addr) {
    asm volatile("ldmatrix.sync.aligned.m8n8.x4.shared.b16 {%0,%1,%2,%3}, [%4];"
                 : "=r"(r0), "=r"(r1), "=r"(r2), "=r"(r3) : "r"(addr));
}

__device__ __forceinline__ void mma16816(float& d0, float& d1, float& d2, float& d3,
                                         uint32_t a0, uint32_t a1, uint32_t a2, uint32_t a3,
                                         uint32_t b0, uint32_t b1) {
    asm volatile("mma.sync.aligned.m16n8k16.row.col.f32.f16.f16.f32 "
                 "{%0,%1,%2,%3}, {%4,%5,%6,%7}, {%8,%9}, {%0,%1,%2,%3};"
                 : "+f"(d0), "+f"(d1), "+f"(d2), "+f"(d3)
                 : "r"(a0), "r"(a1), "r"(a2), "r"(a3), "r"(b0), "r"(b1));
}

// ===========================================================================
// prologue kernels
// ===========================================================================
__global__ void k_init_flag() { if (threadIdx.x == 0) g_is64 = 1; }

__global__ void k_detect(const unsigned long long* __restrict__ f) {
    const int half = BSZ * N_NODES / 2;
    int i = blockIdx.x * blockDim.x + threadIdx.x;
    if (i < half && f[i] >= (unsigned long long)VOCAB) g_is64 = 0;
}

__global__ void k_convert(const void* __restrict__ f) {
    int i = blockIdx.x * blockDim.x + threadIdx.x;
    if (i < BSZ * N_NODES) {
        g_idx32[i] = g_is64 ? (int)((const long long*)f)[i] : ((const int*)f)[i];
    }
}

// W -> fp16
__global__ void k_cvtw(const float* __restrict__ w) {
    int i = blockIdx.x * blockDim.x + threadIdx.x;
    if (i < NO * KDIM) g_whi[i] = __float2half_rn(w[i]);
}

// gather + convert: h[m, node*128+c] = fp16(emb[node, idx[m,node], c])
// one warp per (m, node); lane covers 4 consecutive floats (16B read, 8B write)
__global__ void k_gather(const float* __restrict__ emb) {
    const int gw = (blockIdx.x * blockDim.x + threadIdx.x) >> 5;   // warp id
    const int lane = threadIdx.x & 31;
    if (gw >= BSZ * N_NODES) return;
    const int m = gw / N_NODES;
    const int node = gw - m * N_NODES;
    const int idx = g_idx32[m * N_NODES + node];
    const float4 v = *(const float4*)(emb +
        ((size_t)node * VOCAB + idx) * NI + lane * 4);
    __half2 h0 = __floats2half2_rn(v.x, v.y);
    __half2 h1 = __floats2half2_rn(v.z, v.w);
    uint2 o = { *(uint32_t*)&h0, *(uint32_t*)&h1 };
    *(uint2*)(g_h + (size_t)m * KDIM + node * NI + lane * 4) = o;
}

// ===========================================================================
// dense fp16 HMMA GEMM: out = A_h @ W_h^T + bias, fp32 accumulate
// both operands via cp.async; BK=64; 2 stages; 2 CTAs/SM
// ===========================================================================
__global__ __launch_bounds__(THREADS, 2)
void k_gemm(const float* __restrict__ bias, float* __restrict__ out)
{
    extern __shared__ char smem[];
    const uint32_t sb = (uint32_t)__cvta_generic_to_shared(smem);

    const int tid = threadIdx.x;
    const int wid = tid >> 5;
    const int lid = tid & 31;
    const int m0 = blockIdx.y * BM;
    const int n0 = blockIdx.x * BN;
    const int wm = wid >> 2;       // 0..1 -> warp m block (64 rows)
    const int wn = wid & 3;        // 0..3 -> warp n block (32 cols)

    // producer roles: 2 threads per row, each covers 64B (32 fp16)
    const int prow = tid >> 1;
    const int psel = tid & 1;

    auto issue_stage = [&](int it) {
        if (it < NITER) {
            const uint32_t st = sb + (uint32_t)(it & 1) * STAGE_BYTES;
            const int k0 = it * BK + psel * 32;          // element offset
            const uint32_t da = st + STG_A + (uint32_t)prow * ROWB + (uint32_t)psel * 64;
            const __half* sa = g_h + (size_t)(m0 + prow) * KDIM + k0;
            cpa16(da,      sa);
            cpa16(da + 16, sa + 8);
            cpa16(da + 32, sa + 16);
            cpa16(da + 48, sa + 24);
            const uint32_t db = st + STG_B + (uint32_t)prow * ROWB + (uint32_t)psel * 64;
            const __half* sbp = g_whi + (size_t)(n0 + prow) * KDIM + k0;
            cpa16(db,      sbp);
            cpa16(db + 16, sbp + 8);
            cpa16(db + 32, sbp + 16);
            cpa16(db + 48, sbp + 24);
            cpa_commit();
        }
    };

    float acc[4][4][4];
    #pragma unroll
    for (int i = 0; i < 4; i++)
        #pragma unroll
        for (int j = 0; j < 4; j++)
            #pragma unroll
            for (int q = 0; q < 4; q++)
                acc[i][j][q] = 0.0f;

    issue_stage(0);

    const uint32_t lrow = (uint32_t)(lid & 15);
    const uint32_t lcolh = (uint32_t)((lid >> 4) * 16);

    for (int it = 0; it < NITER; it++) {
        const uint32_t st = sb + (uint32_t)(it & 1) * STAGE_BYTES;

        // group(it) is the only outstanding group here (group(it+1) not yet issued)
        cpa_wait_all();
        __syncthreads();           // cp.async data visible to all; compute(it-1) done

        issue_stage(it + 1);       // into stage (it+1)&1 — safe post-barrier

        #pragma unroll
        for (int ks = 0; ks < 4; ks++) {
            const uint32_t cb = (uint32_t)ks * 32;      // 16 fp16 = 32B per k16 step
            uint32_t ah[4][4], bhf[2][4];
            #pragma unroll
            for (int mi = 0; mi < 4; mi++) {
                const uint32_t ra = st + STG_A +
                    (uint32_t)(wm * 64 + mi * 16 + lrow) * ROWB + cb + lcolh;
                ldmx4(ah[mi][0], ah[mi][1], ah[mi][2], ah[mi][3], ra);
            }
            #pragma unroll
            for (int p = 0; p < 2; p++) {
                const uint32_t rb = st + STG_B +
                    (uint32_t)(wn * 32 + p * 16 + lrow) * ROWB + cb + lcolh;
                ldmx4(bhf[p][0], bhf[p][1], bhf[p][2], bhf[p][3], rb);
            }
            #pragma unroll
            for (int mi = 0; mi < 4; mi++) {
                #pragma unroll
                for (int p = 0; p < 2; p++) {
                    mma16816(acc[mi][2*p][0], acc[mi][2*p][1], acc[mi][2*p][2], acc[mi][2*p][3],
                             ah[mi][0], ah[mi][1], ah[mi][2], ah[mi][3], bhf[p][0], bhf[p][2]);
                    mma16816(acc[mi][2*p+1][0], acc[mi][2*p+1][1], acc[mi][2*p+1][2], acc[mi][2*p+1][3],
                             ah[mi][0], ah[mi][1], ah[mi][2], ah[mi][3], bhf[p][1], bhf[p][3]);
                }
            }
        }
    }

    // ---- epilogue: acc -> global with bias ----
    const int gid = lid >> 2;
    const int tig = lid & 3;
    #pragma unroll
    for (int mi = 0; mi < 4; mi++) {
        const int r0 = m0 + wm * 64 + mi * 16 + gid;
        #pragma unroll
        for (int ni = 0; ni < 4; ni++) {
            const int c = n0 + wn * 32 + ni * 8 + tig * 2;
            const float2 bb = *(const float2*)(bias + c);
            float2 v0 = { acc[mi][ni][0] + bb.x, acc[mi][ni][1] + bb.y };
            float2 v1 = { acc[mi][ni][2] + bb.x, acc[mi][ni][3] + bb.y };
            *(float2*)(out + (size_t)r0 * NO + c) = v0;
            *(float2*)(out + (size_t)(r0 + 8) * NO + c) = v1;
        }
    }
}

// ===========================================================================
extern "C" void kernel_launch(void* const* d_in, const int* in_sizes, int n_in,
                              void* d_out, int out_size)
{
    (void)in_sizes; (void)n_in; (void)out_size;
    const void*  feat = d_in[0];
    const float* emb  = (const float*)d_in[1];
    const float* w    = (const float*)d_in[2];
    const float* bias = (const float*)d_in[3];
    float* out = (float*)d_out;

    k_init_flag<<<1, 32>>>();
    {
        const int half = BSZ * N_NODES / 2;
        k_detect<<<(half + 255) / 256, 256>>>((const unsigned long long*)feat);
    }
    k_convert<<<(BSZ * N_NODES + 255) / 256, 256>>>(feat);
    k_cvtw<<<(NO * KDIM + 255) / 256, 256>>>(w);
    {
        const int nwarps = BSZ * N_NODES;                 // one warp per (m, node)
        k_gather<<<(nwarps * 32 + 255) / 256, 256>>>(emb);
    }

    cudaFuncSetAttribute(k_gemm, cudaFuncAttributeMaxDynamicSharedMemorySize, SMEM_ALLOC);

    dim3 grid(NO / BN, BSZ / BM);   // (4, 128)
    k_gemm<<<grid, THREADS, SMEM_ALLOC>>>(bias, out);
}

// round 15
// speedup vs baseline: 4.0404x; 1.0143x over previous
#include <cuda_runtime.h>
#include <cuda_fp16.h>
#include <cstdint>
#include <cstddef>

#define N_NODES 19
#define NI      128
#define NO      512
#define KDIM    2432
#define BSZ     16384
#define VOCAB   20000

#define BM      128
#define BN      128
#define BK      64                 // fp16 k-chunk
#define NITER   (KDIM / BK)        // 38
#define THREADS 256
#define STAGES  3

// ---- dynamic smem layout ----
#define ROWB        144                     // 128B data + 16B pad (16B-aligned, conflict-free)
#define STG_A       0                       // 128*144 = 18432 B
#define STG_B       18432
#define STAGE_BYTES 36864
#define SMEM_ALLOC  (STAGES * STAGE_BYTES)  // 110592  (x2 CTAs = 221KB/SM <= 228KB)

// ---- global scratch ----
__device__ int g_idx32[BSZ * N_NODES];
__device__ int g_is64;
__device__ __align__(16) __half g_whi[NO * KDIM];
__device__ __align__(16) __half g_h[(size_t)BSZ * KDIM];   // gathered A, fp16 (76MB)

// ===========================================================================
// helpers
// ===========================================================================
__device__ __forceinline__ void cpa16(uint32_t dst, const void* src) {
    asm volatile("cp.async.cg.shared.global [%0], [%1], 16;"
                 :: "r"(dst), "l"(src) : "memory");
}
__device__ __forceinline__ void cpa_commit() {
    asm volatile("cp.async.commit_group;" ::: "memory");
}
template <int N>
__device__ __forceinline__ void cpa_wait() {
    asm volatile("cp.async.wait_group %0;" :: "n"(N) : "memory");
}

__device__ __forceinline__ void ldmx4(uint32_t& r0, uint32_t& r1, uint32_t& r2,
                                      uint32_t& r3, uint32_t addr) {
    asm volatile("ldmatrix.sync.aligned.m8n8.x4.shared.b16 {%0,%1,%2,%3}, [%4];"
                 : "=r"(r0), "=r"(r1), "=r"(r2), "=r"(r3) : "r"(addr));
}

__device__ __forceinline__ void mma16816(float& d0, float& d1, float& d2, float& d3,
                                         uint32_t a0, uint32_t a1, uint32_t a2, uint32_t a3,
                                         uint32_t b0, uint32_t b1) {
    asm volatile("mma.sync.aligned.m16n8k16.row.col.f32.f16.f16.f32 "
                 "{%0,%1,%2,%3}, {%4,%5,%6,%7}, {%8,%9}, {%0,%1,%2,%3};"
                 : "+f"(d0), "+f"(d1), "+f"(d2), "+f"(d3)
                 : "r"(a0), "r"(a1), "r"(a2), "r"(a3), "r"(b0), "r"(b1));
}

// ===========================================================================
// prologue kernels
// ===========================================================================
__global__ void k_init_flag() { if (threadIdx.x == 0) g_is64 = 1; }

__global__ void k_detect(const unsigned long long* __restrict__ f) {
    const int half = BSZ * N_NODES / 2;
    int i = blockIdx.x * blockDim.x + threadIdx.x;
    if (i < half && f[i] >= (unsigned long long)VOCAB) g_is64 = 0;
}

__global__ void k_convert(const void* __restrict__ f) {
    int i = blockIdx.x * blockDim.x + threadIdx.x;
    if (i < BSZ * N_NODES) {
        g_idx32[i] = g_is64 ? (int)((const long long*)f)[i] : ((const int*)f)[i];
    }
}

// W -> fp16
__global__ void k_cvtw(const float* __restrict__ w) {
    int i = blockIdx.x * blockDim.x + threadIdx.x;
    if (i < NO * KDIM) g_whi[i] = __float2half_rn(w[i]);
}

// gather + convert: h[m, node*128+c] = fp16(emb[node, idx[m,node], c])
// one warp per (m, node); lane covers 4 consecutive floats
__global__ void k_gather(const float* __restrict__ emb) {
    const int gw = (blockIdx.x * blockDim.x + threadIdx.x) >> 5;
    const int lane = threadIdx.x & 31;
    if (gw >= BSZ * N_NODES) return;
    const int m = gw / N_NODES;
    const int node = gw - m * N_NODES;
    const int idx = g_idx32[m * N_NODES + node];
    const float4 v = *(const float4*)(emb +
        ((size_t)node * VOCAB + idx) * NI + lane * 4);
    __half2 h0 = __floats2half2_rn(v.x, v.y);
    __half2 h1 = __floats2half2_rn(v.z, v.w);
    uint2 o = { *(uint32_t*)&h0, *(uint32_t*)&h1 };
    *(uint2*)(g_h + (size_t)m * KDIM + node * NI + lane * 4) = o;
}

// ===========================================================================
// dense fp16 HMMA GEMM: out = A_h @ W_h^T + bias, fp32 accumulate
// cp.async both operands; BK=64; 3 stages, wait_group<1>; 2 CTAs/SM
// ===========================================================================
__global__ __launch_bounds__(THREADS, 2)
void k_gemm(const float* __restrict__ bias, float* __restrict__ out)
{
    extern __shared__ char smem[];
    const uint32_t sb = (uint32_t)__cvta_generic_to_shared(smem);

    const int tid = threadIdx.x;
    const int wid = tid >> 5;
    const int lid = tid & 31;
    const int m0 = blockIdx.y * BM;
    const int n0 = blockIdx.x * BN;
    const int wm = wid >> 2;       // 0..1 -> warp m block (64 rows)
    const int wn = wid & 3;        // 0..3 -> warp n block (32 cols)

    // producer roles: 2 threads per row, each covers 64B (32 fp16)
    const int prow = tid >> 1;
    const int psel = tid & 1;

    // stage slot for iteration it: it % 3
    auto issue_stage = [&](int it, int slot) {
        if (it < NITER) {
            const uint32_t st = sb + (uint32_t)slot * STAGE_BYTES;
            const int k0 = it * BK + psel * 32;
            const uint32_t da = st + STG_A + (uint32_t)prow * ROWB + (uint32_t)psel * 64;
            const __half* sa = g_h + (size_t)(m0 + prow) * KDIM + k0;
            cpa16(da,      sa);
            cpa16(da + 16, sa + 8);
            cpa16(da + 32, sa + 16);
            cpa16(da + 48, sa + 24);
            const uint32_t db = st + STG_B + (uint32_t)prow * ROWB + (uint32_t)psel * 64;
            const __half* sbp = g_whi + (size_t)(n0 + prow) * KDIM + k0;
            cpa16(db,      sbp);
            cpa16(db + 16, sbp + 8);
            cpa16(db + 32, sbp + 16);
            cpa16(db + 48, sbp + 24);
        }
        cpa_commit();   // ALWAYS commit (possibly empty) to keep group-count invariant
    };

    float acc[4][4][4];
    #pragma unroll
    for (int i = 0; i < 4; i++)
        #pragma unroll
        for (int j = 0; j < 4; j++)
            #pragma unroll
            for (int q = 0; q < 4; q++)
                acc[i][j][q] = 0.0f;

    issue_stage(0, 0);
    issue_stage(1, 1);

    const uint32_t lrow = (uint32_t)(lid & 15);
    const uint32_t lcolh = (uint32_t)((lid >> 4) * 16);

    int slot = 0;
    for (int it = 0; it < NITER; it++) {
        const uint32_t st = sb + (uint32_t)slot * STAGE_BYTES;

        // committed groups so far: 0..it+1; <=1 pending => group(it) landed,
        // group(it+1) may still be in flight (two compute phases of slack)
        cpa_wait<1>();
        __syncthreads();           // data visible to all; compute(it-1) done

        {
            int nslot = slot + 2; if (nslot >= STAGES) nslot -= STAGES;
            issue_stage(it + 2, nslot);   // slot (it+2)%3 == slot(it-1) — free post-barrier
        }

        #pragma unroll
        for (int ks = 0; ks < 4; ks++) {
            const uint32_t cb = (uint32_t)ks * 32;
            uint32_t ah[4][4], bhf[2][4];
            #pragma unroll
            for (int mi = 0; mi < 4; mi++) {
                const uint32_t ra = st + STG_A +
                    (uint32_t)(wm * 64 + mi * 16 + lrow) * ROWB + cb + lcolh;
                ldmx4(ah[mi][0], ah[mi][1], ah[mi][2], ah[mi][3], ra);
            }
            #pragma unroll
            for (int p = 0; p < 2; p++) {
                const uint32_t rb = st + STG_B +
                    (uint32_t)(wn * 32 + p * 16 + lrow) * ROWB + cb + lcolh;
                ldmx4(bhf[p][0], bhf[p][1], bhf[p][2], bhf[p][3], rb);
            }
            #pragma unroll
            for (int mi = 0; mi < 4; mi++) {
                #pragma unroll
                for (int p = 0; p < 2; p++) {
                    mma16816(acc[mi][2*p][0], acc[mi][2*p][1], acc[mi][2*p][2], acc[mi][2*p][3],
                             ah[mi][0], ah[mi][1], ah[mi][2], ah[mi][3], bhf[p][0], bhf[p][2]);
                    mma16816(acc[mi][2*p+1][0], acc[mi][2*p+1][1], acc[mi][2*p+1][2], acc[mi][2*p+1][3],
                             ah[mi][0], ah[mi][1], ah[mi][2], ah[mi][3], bhf[p][1], bhf[p][3]);
                }
            }
        }

        slot++; if (slot >= STAGES) slot = 0;
    }

    // ---- epilogue: acc -> global with bias ----
    const int gid = lid >> 2;
    const int tig = lid & 3;
    #pragma unroll
    for (int mi = 0; mi < 4; mi++) {
        const int r0 = m0 + wm * 64 + mi * 16 + gid;
        #pragma unroll
        for (int ni = 0; ni < 4; ni++) {
            const int c = n0 + wn * 32 + ni * 8 + tig * 2;
            const float2 bb = *(const float2*)(bias + c);
            float2 v0 = { acc[mi][ni][0] + bb.x, acc[mi][ni][1] + bb.y };
            float2 v1 = { acc[mi][ni][2] + bb.x, acc[mi][ni][3] + bb.y };
            *(float2*)(out + (size_t)r0 * NO + c) = v0;
            *(float2*)(out + (size_t)(r0 + 8) * NO + c) = v1;
        }
    }
}

// ===========================================================================
extern "C" void kernel_launch(void* const* d_in, const int* in_sizes, int n_in,
                              void* d_out, int out_size)
{
    (void)in_sizes; (void)n_in; (void)out_size;
    const void*  feat = d_in[0];
    const float* emb  = (const float*)d_in[1];
    const float* w    = (const float*)d_in[2];
    const float* bias = (const float*)d_in[3];
    float* out = (float*)d_out;

    k_init_flag<<<1, 32>>>();
    {
        const int half = BSZ * N_NODES / 2;
        k_detect<<<(half + 255) / 256, 256>>>((const unsigned long long*)feat);
    }
    k_convert<<<(BSZ * N_NODES + 255) / 256, 256>>>(feat);
    k_cvtw<<<(NO * KDIM + 255) / 256, 256>>>(w);
    {
        const int nwarps = BSZ * N_NODES;
        k_gather<<<(nwarps * 32 + 255) / 256, 256>>>(emb);
    }

    cudaFuncSetAttribute(k_gemm, cudaFuncAttributeMaxDynamicSharedMemorySize, SMEM_ALLOC);

    dim3 grid(NO / BN, BSZ / BM);   // (4, 128)
    k_gemm<<<grid, THREADS, SMEM_ALLOC>>>(bias, out);
}

// round 16
// speedup vs baseline: 4.0454x; 1.0012x over previous
#include <cuda_runtime.h>
#include <cuda_fp16.h>
#include <cstdint>
#include <cstddef>

#define N_NODES 19
#define NI      128
#define NO      512
#define KDIM    2432
#define BSZ     16384
#define VOCAB   20000

#define BM      128
#define BN      128
#define BK      64                 // fp16 k-chunk
#define NITER   (KDIM / BK)        // 38
#define THREADS 256
#define STAGES  3

// ---- dynamic smem layout ----
#define ROWB        144                     // 128B data + 16B pad (16B-aligned, conflict-free)
#define STG_A       0                       // 128*144 = 18432 B
#define STG_B       18432
#define STAGE_BYTES 36864
#define SMEM_ALLOC  (STAGES * STAGE_BYTES)  // 110592  (x2 CTAs = 221KB/SM <= 228KB)

// ---- global scratch ----
__device__ int g_idx32[BSZ * N_NODES];
__device__ int g_is64;
__device__ __align__(16) __half g_whi[NO * KDIM];
__device__ __align__(16) __half g_h[(size_t)BSZ * KDIM];   // gathered A, fp16 (76MB)

// ===========================================================================
// helpers
// ===========================================================================
__device__ __forceinline__ void cpa16(uint32_t dst, const void* src) {
    asm volatile("cp.async.cg.shared.global [%0], [%1], 16;"
                 :: "r"(dst), "l"(src) : "memory");
}
__device__ __forceinline__ void cpa_commit() {
    asm volatile("cp.async.commit_group;" ::: "memory");
}
template <int N>
__device__ __forceinline__ void cpa_wait() {
    asm volatile("cp.async.wait_group %0;" :: "n"(N) : "memory");
}

__device__ __forceinline__ void ldmx4(uint32_t& r0, uint32_t& r1, uint32_t& r2,
                                      uint32_t& r3, uint32_t addr) {
    asm volatile("ldmatrix.sync.aligned.m8n8.x4.shared.b16 {%0,%1,%2,%3}, [%4];"
                 : "=r"(r0), "=r"(r1), "=r"(r2), "=r"(r3) : "r"(addr));
}

__device__ __forceinline__ void mma16816(float& d0, float& d1, float& d2, float& d3,
                                         uint32_t a0, uint32_t a1, uint32_t a2, uint32_t a3,
                                         uint32_t b0, uint32_t b1) {
    asm volatile("mma.sync.aligned.m16n8k16.row.col.f32.f16.f16.f32 "
                 "{%0,%1,%2,%3}, {%4,%5,%6,%7}, {%8,%9}, {%0,%1,%2,%3};"
                 : "+f"(d0), "+f"(d1), "+f"(d2), "+f"(d3)
                 : "r"(a0), "r"(a1), "r"(a2), "r"(a3), "r"(b0), "r"(b1));
}

// ===========================================================================
// prologue kernels
// ===========================================================================
__global__ void k_init_flag() { if (threadIdx.x == 0) g_is64 = 1; }

__global__ void k_detect(const unsigned long long* __restrict__ f) {
    const int half = BSZ * N_NODES / 2;
    int i = blockIdx.x * blockDim.x + threadIdx.x;
    if (i < half && f[i] >= (unsigned long long)VOCAB) g_is64 = 0;
}

__global__ void k_convert(const void* __restrict__ f) {
    int i = blockIdx.x * blockDim.x + threadIdx.x;
    if (i < BSZ * N_NODES) {
        g_idx32[i] = g_is64 ? (int)((const long long*)f)[i] : ((const int*)f)[i];
    }
}

// W -> fp16
__global__ void k_cvtw(const float* __restrict__ w) {
    int i = blockIdx.x * blockDim.x + threadIdx.x;
    if (i < NO * KDIM) g_whi[i] = __float2half_rn(w[i]);
}

// gather + convert: h[m, node*128+c] = fp16(emb[node, idx[m,node], c])
// one warp per (m, node); lane covers 4 consecutive floats
__global__ void k_gather(const float* __restrict__ emb) {
    const int gw = (blockIdx.x * blockDim.x + threadIdx.x) >> 5;
    const int lane = threadIdx.x & 31;
    if (gw >= BSZ * N_NODES) return;
    const int m = gw / N_NODES;
    const int node = gw - m * N_NODES;
    const int idx = g_idx32[m * N_NODES + node];
    const float4 v = *(const float4*)(emb +
        ((size_t)node * VOCAB + idx) * NI + lane * 4);
    __half2 h0 = __floats2half2_rn(v.x, v.y);
    __half2 h1 = __floats2half2_rn(v.z, v.w);
    uint2 o = { *(uint32_t*)&h0, *(uint32_t*)&h1 };
    *(uint2*)(g_h + (size_t)m * KDIM + node * NI + lane * 4) = o;
}

// ===========================================================================
// dense fp16 HMMA GEMM: out = A_h @ W_h^T + bias, fp32 accumulate
// cp.async both operands; BK=64; 3 stages, wait_group<1>; 2 CTAs/SM
// ===========================================================================
__global__ __launch_bounds__(THREADS, 2)
void k_gemm(const float* __restrict__ bias, float* __restrict__ out)
{
    extern __shared__ char smem[];
    const uint32_t sb = (uint32_t)__cvta_generic_to_shared(smem);

    const int tid = threadIdx.x;
    const int wid = tid >> 5;
    const int lid = tid & 31;
    const int m0 = blockIdx.y * BM;
    const int n0 = blockIdx.x * BN;
    const int wm = wid >> 2;       // 0..1 -> warp m block (64 rows)
    const int wn = wid & 3;        // 0..3 -> warp n block (32 cols)

    // producer roles: 2 threads per row, each covers 64B (32 fp16)
    const int prow = tid >> 1;
    const int psel = tid & 1;

    // stage slot for iteration it: it % 3
    auto issue_stage = [&](int it, int slot) {
        if (it < NITER) {
            const uint32_t st = sb + (uint32_t)slot * STAGE_BYTES;
            const int k0 = it * BK + psel * 32;
            const uint32_t da = st + STG_A + (uint32_t)prow * ROWB + (uint32_t)psel * 64;
            const __half* sa = g_h + (size_t)(m0 + prow) * KDIM + k0;
            cpa16(da,      sa);
            cpa16(da + 16, sa + 8);
            cpa16(da + 32, sa + 16);
            cpa16(da + 48, sa + 24);
            const uint32_t db = st + STG_B + (uint32_t)prow * ROWB + (uint32_t)psel * 64;
            const __half* sbp = g_whi + (size_t)(n0 + prow) * KDIM + k0;
            cpa16(db,      sbp);
            cpa16(db + 16, sbp + 8);
            cpa16(db + 32, sbp + 16);
            cpa16(db + 48, sbp + 24);
        }
        cpa_commit();   // ALWAYS commit (possibly empty) to keep group-count invariant
    };

    float acc[4][4][4];
    #pragma unroll
    for (int i = 0; i < 4; i++)
        #pragma unroll
        for (int j = 0; j < 4; j++)
            #pragma unroll
            for (int q = 0; q < 4; q++)
                acc[i][j][q] = 0.0f;

    issue_stage(0, 0);
    issue_stage(1, 1);

    const uint32_t lrow = (uint32_t)(lid & 15);
    const uint32_t lcolh = (uint32_t)((lid >> 4) * 16);

    int slot = 0;
    for (int it = 0; it < NITER; it++) {
        const uint32_t st = sb + (uint32_t)slot * STAGE_BYTES;

        // committed groups so far: 0..it+1; <=1 pending => group(it) landed,
        // group(it+1) may still be in flight (two compute phases of slack)
        cpa_wait<1>();
        __syncthreads();           // data visible to all; compute(it-1) done

        {
            int nslot = slot + 2; if (nslot >= STAGES) nslot -= STAGES;
            issue_stage(it + 2, nslot);   // slot (it+2)%3 == slot(it-1) — free post-barrier
        }

        #pragma unroll
        for (int ks = 0; ks < 4; ks++) {
            const uint32_t cb = (uint32_t)ks * 32;
            uint32_t ah[4][4], bhf[2][4];
            #pragma unroll
            for (int mi = 0; mi < 4; mi++) {
                const uint32_t ra = st + STG_A +
                    (uint32_t)(wm * 64 + mi * 16 + lrow) * ROWB + cb + lcolh;
                ldmx4(ah[mi][0], ah[mi][1], ah[mi][2], ah[mi][3], ra);
            }
            #pragma unroll
            for (int p = 0; p < 2; p++) {
                const uint32_t rb = st + STG_B +
                    (uint32_t)(wn * 32 + p * 16 + lrow) * ROWB + cb + lcolh;
                ldmx4(bhf[p][0], bhf[p][1], bhf[p][2], bhf[p][3], rb);
            }
            #pragma unroll
            for (int mi = 0; mi < 4; mi++) {
                #pragma unroll
                for (int p = 0; p < 2; p++) {
                    mma16816(acc[mi][2*p][0], acc[mi][2*p][1], acc[mi][2*p][2], acc[mi][2*p][3],
                             ah[mi][0], ah[mi][1], ah[mi][2], ah[mi][3], bhf[p][0], bhf[p][2]);
                    mma16816(acc[mi][2*p+1][0], acc[mi][2*p+1][1], acc[mi][2*p+1][2], acc[mi][2*p+1][3],
                             ah[mi][0], ah[mi][1], ah[mi][2], ah[mi][3], bhf[p][1], bhf[p][3]);
                }
            }
        }

        slot++; if (slot >= STAGES) slot = 0;
    }

    // ---- epilogue: acc -> global with bias ----
    const int gid = lid >> 2;
    const int tig = lid & 3;
    #pragma unroll
    for (int mi = 0; mi < 4; mi++) {
        const int r0 = m0 + wm * 64 + mi * 16 + gid;
        #pragma unroll
        for (int ni = 0; ni < 4; ni++) {
            const int c = n0 + wn * 32 + ni * 8 + tig * 2;
            const float2 bb = *(const float2*)(bias + c);
            float2 v0 = { acc[mi][ni][0] + bb.x, acc[mi][ni][1] + bb.y };
            float2 v1 = { acc[mi][ni][2] + bb.x, acc[mi][ni][3] + bb.y };
            *(float2*)(out + (size_t)r0 * NO + c) = v0;
            *(float2*)(out + (size_t)(r0 + 8) * NO + c) = v1;
        }
    }
}

// ===========================================================================
extern "C" void kernel_launch(void* const* d_in, const int* in_sizes, int n_in,
                              void* d_out, int out_size)
{
    (void)in_sizes; (void)n_in; (void)out_size;
    const void*  feat = d_in[0];
    const float* emb  = (const float*)d_in[1];
    const float* w    = (const float*)d_in[2];
    const float* bias = (const float*)d_in[3];
    float* out = (float*)d_out;

    k_init_flag<<<1, 32>>>();
    {
        const int half = BSZ * N_NODES / 2;
        k_detect<<<(half + 255) / 256, 256>>>((const unsigned long long*)feat);
    }
    k_convert<<<(BSZ * N_NODES + 255) / 256, 256>>>(feat);
    k_cvtw<<<(NO * KDIM + 255) / 256, 256>>>(w);
    {
        const int nwarps = BSZ * N_NODES;
        k_gather<<<(nwarps * 32 + 255) / 256, 256>>>(emb);
    }

    cudaFuncSetAttribute(k_gemm, cudaFuncAttributeMaxDynamicSharedMemorySize, SMEM_ALLOC);

    dim3 grid(NO / BN, BSZ / BM);   // (4, 128)
    k_gemm<<<grid, THREADS, SMEM_ALLOC>>>(bias, out);
}